// round 2
// baseline (speedup 1.0000x reference)
#include <cuda_runtime.h>

#define Mn   4096
#define NNB  16
#define Gn   4
#define INF  32
#define OUTF 32
#define LOCF 8
#define LHID 128
#define Bn   16
#define NP   (Mn * NNB)   // 65536 node-neighbor pairs

// ---------------- device scratch (static, zero-initialized at load) ----------
__device__ float4 d_attn4[NP];              // attn[n] packed over g (x,y,z,w = g0..g3)
__device__ int    d_winner[Mn * Mn];        // stores n+1 of last writer; 0 = empty (64MB)
__device__ int    d_counts[Mn];
__device__ int    d_rowPtr[Mn + 1];
__device__ int    d_cursor[Mn];
__device__ int    d_elist[NP];
__device__ float  d_agg[(size_t)Bn * Mn * Gn * INF];   // [b*M+i][g*32+f], 32MB

// ---------------- Stage 1: edge MLP + per-node softmax -----------------------
// grid 512 blocks x 512 threads; block handles 8 nodes x 16 nn x 4 g = 512 pairs
__global__ void __launch_bounds__(512) k_attn(
    const float* __restrict__ maps, const float* __restrict__ W1,
    const float* __restrict__ b1,   const float* __restrict__ W2,
    const float* __restrict__ b2)
{
    __shared__ float4 sW1[Gn * LHID * 2];   // W1 row (8 floats) as 2x float4
    __shared__ float2 sWB[Gn * LHID];       // (W2[k], b1[k])

    int t = threadIdx.x;
    for (int i = t; i < Gn * LHID * 2; i += 512) sW1[i] = ((const float4*)W1)[i];
    for (int i = t; i < Gn * LHID;     i += 512) sWB[i] = make_float2(W2[i], b1[i]);
    __syncthreads();

    int nodeL = t >> 6;            // 0..7
    int g     = (t >> 4) & 3;      // 0..3
    int nn    = t & 15;            // 0..15
    int node  = blockIdx.x * 8 + nodeL;
    int n     = node * NNB + nn;

    const float4* mp = (const float4*)(maps + (size_t)n * LOCF);
    float4 m0 = mp[0], m1 = mp[1];

    float ctx = b2[g];
    int base = g * LHID;
    #pragma unroll 4
    for (int k = 0; k < LHID; k++) {
        float4 wa = sW1[(base + k) * 2];
        float4 wb = sW1[(base + k) * 2 + 1];
        float2 w2b1 = sWB[base + k];
        float pre = w2b1.y
                  + m0.x * wa.x + m0.y * wa.y + m0.z * wa.z + m0.w * wa.w
                  + m1.x * wb.x + m1.y * wb.y + m1.z * wb.z + m1.w * wb.w;
        // tanh(pre) = 1 - 2/(exp(2*pre)+1); exact at +-inf, ~1e-6 rel error
        float e  = __expf(2.0f * pre);
        float th = 1.0f - __fdividef(2.0f, e + 1.0f);
        ctx = fmaf(w2b1.x, th, ctx);
    }

    // softmax over the 16 nn of (node, g): groups of 16 consecutive lanes
    float mx = ctx;
    #pragma unroll
    for (int o = 8; o; o >>= 1) mx = fmaxf(mx, __shfl_xor_sync(0xffffffffu, mx, o));
    float ev = __expf(ctx - mx);
    float s = ev;
    #pragma unroll
    for (int o = 8; o; o >>= 1) s += __shfl_xor_sync(0xffffffffu, s, o);
    ((float*)d_attn4)[(size_t)n * 4 + g] = ev / s;
}

// ---------------- Stage 2: duplicate resolution + CSR build ------------------
__global__ void k_winner(const int* __restrict__ L_idx) {
    int n = blockIdx.x * 256 + threadIdx.x;
    atomicMax(&d_winner[L_idx[n]], n + 1);
}

__global__ void k_count(const int* __restrict__ L_idx) {
    int n = blockIdx.x * 256 + threadIdx.x;
    int idx = L_idx[n];
    if (d_winner[idx] == n + 1) atomicAdd(&d_counts[idx >> 12], 1);
}

__global__ void __launch_bounds__(1024) k_scan() {
    __shared__ int s[1024];
    int t = threadIdx.x;
    int c0 = d_counts[t * 4 + 0], c1 = d_counts[t * 4 + 1];
    int c2 = d_counts[t * 4 + 2], c3 = d_counts[t * 4 + 3];
    int p1 = c0, p2 = c0 + c1, p3 = c0 + c1 + c2, tot = p3 + c3;
    s[t] = tot;
    __syncthreads();
    for (int off = 1; off < 1024; off <<= 1) {
        int v = (t >= off) ? s[t - off] : 0;
        __syncthreads();
        s[t] += v;
        __syncthreads();
    }
    int bpre = t ? s[t - 1] : 0;
    d_rowPtr[t * 4 + 0] = bpre;      d_cursor[t * 4 + 0] = bpre;
    d_rowPtr[t * 4 + 1] = bpre + p1; d_cursor[t * 4 + 1] = bpre + p1;
    d_rowPtr[t * 4 + 2] = bpre + p2; d_cursor[t * 4 + 2] = bpre + p2;
    d_rowPtr[t * 4 + 3] = bpre + p3; d_cursor[t * 4 + 3] = bpre + p3;
    if (t == 1023) d_rowPtr[Mn] = s[1023];
}

__global__ void k_fill(const int* __restrict__ L_idx) {
    int n = blockIdx.x * 256 + threadIdx.x;
    int idx = L_idx[n];
    if (d_winner[idx] == n + 1) {
        int pos = atomicAdd(&d_cursor[idx >> 12], 1);
        d_elist[pos] = n;
    }
}

// ---------------- Stage 3: row-gather aggregation ----------------------------
// one block per row i; thread = (b, f-pair); 8 accumulators (4 g x 2 f)
__global__ void __launch_bounds__(256) k_agg(
    const int* __restrict__ L_idx, const float* __restrict__ x)
{
    int i = blockIdx.x;
    int t = threadIdx.x;
    int b = t >> 4, fh = t & 15;
    int e0 = d_rowPtr[i], e1 = d_rowPtr[i + 1];

    float2 acc0 = {0.f, 0.f}, acc1 = {0.f, 0.f}, acc2 = {0.f, 0.f}, acc3 = {0.f, 0.f};
    const float2* x2 = (const float2*)x;

    for (int e = e0; e < e1; e++) {
        int n = d_elist[e];
        int j = L_idx[n] & (Mn - 1);
        float4 a = d_attn4[n];
        float2 xv = x2[(size_t)(b * Mn + j) * 16 + fh];
        acc0.x = fmaf(a.x, xv.x, acc0.x); acc0.y = fmaf(a.x, xv.y, acc0.y);
        acc1.x = fmaf(a.y, xv.x, acc1.x); acc1.y = fmaf(a.y, xv.y, acc1.y);
        acc2.x = fmaf(a.z, xv.x, acc2.x); acc2.y = fmaf(a.z, xv.y, acc2.y);
        acc3.x = fmaf(a.w, xv.x, acc3.x); acc3.y = fmaf(a.w, xv.y, acc3.y);
    }

    float2* agg2 = (float2*)d_agg;
    size_t rbase = (size_t)(b * Mn + i) * 64 + fh;   // [r][g*16+fh] in float2
    agg2[rbase + 0 * 16] = acc0;
    agg2[rbase + 1 * 16] = acc1;
    agg2[rbase + 2 * 16] = acc2;
    agg2[rbase + 3 * 16] = acc3;
}

// ---------------- Stage 4: dense GEMM (65536x128)@(128x32)+bx ----------------
// block: 256 rows x 32 cols; thread: 8 rows x 4 cols
__global__ void __launch_bounds__(256) k_gemm(
    const float* __restrict__ Wx, const float* __restrict__ bx,
    float* __restrict__ out)
{
    __shared__ float4 sW[LHID * 8];    // Wx[k][o] as float4 over o: sW[k*8 + oc]
    int t = threadIdx.x;
    for (int i = t; i < LHID * 8; i += 256) sW[i] = ((const float4*)Wx)[i];
    __syncthreads();

    int tcol = t & 7;        // o block: [tcol*4, tcol*4+4)
    int trow = t >> 3;       // 0..31
    int r0 = blockIdx.x * 256 + trow * 8;

    const float4* A4 = (const float4*)d_agg;
    float4 acc[8];
    #pragma unroll
    for (int rr = 0; rr < 8; rr++) acc[rr] = make_float4(0.f, 0.f, 0.f, 0.f);

    #pragma unroll 1
    for (int k4 = 0; k4 < 32; k4++) {
        float4 w0 = sW[(k4 * 4 + 0) * 8 + tcol];
        float4 w1 = sW[(k4 * 4 + 1) * 8 + tcol];
        float4 w2 = sW[(k4 * 4 + 2) * 8 + tcol];
        float4 w3 = sW[(k4 * 4 + 3) * 8 + tcol];
        #pragma unroll
        for (int rr = 0; rr < 8; rr++) {
            float4 av = A4[(size_t)(r0 + rr) * 32 + k4];
            acc[rr].x = fmaf(av.x, w0.x, fmaf(av.y, w1.x, fmaf(av.z, w2.x, fmaf(av.w, w3.x, acc[rr].x))));
            acc[rr].y = fmaf(av.x, w0.y, fmaf(av.y, w1.y, fmaf(av.z, w2.y, fmaf(av.w, w3.y, acc[rr].y))));
            acc[rr].z = fmaf(av.x, w0.z, fmaf(av.y, w1.z, fmaf(av.z, w2.z, fmaf(av.w, w3.z, acc[rr].z))));
            acc[rr].w = fmaf(av.x, w0.w, fmaf(av.y, w1.w, fmaf(av.z, w2.w, fmaf(av.w, w3.w, acc[rr].w))));
        }
    }

    float4 bxv = ((const float4*)bx)[tcol];
    #pragma unroll
    for (int rr = 0; rr < 8; rr++) {
        float4 v;
        v.x = acc[rr].x + bxv.x; v.y = acc[rr].y + bxv.y;
        v.z = acc[rr].z + bxv.z; v.w = acc[rr].w + bxv.w;
        ((float4*)out)[(size_t)(r0 + rr) * 8 + tcol] = v;
    }
}

// ---------------- cleanup: restore scratch invariants for next launch --------
__global__ void k_clean(const int* __restrict__ L_idx) {
    int n = blockIdx.x * 256 + threadIdx.x;
    d_winner[L_idx[n]] = 0;
    if (n < Mn) d_counts[n] = 0;
}

// ---------------- launch ------------------------------------------------------
extern "C" void kernel_launch(void* const* d_in, const int* in_sizes, int n_in,
                              void* d_out, int out_size)
{
    const float* x    = (const float*)d_in[0];
    const float* maps = (const float*)d_in[1];
    const int*   Lix  = (const int*)  d_in[2];
    const float* W1   = (const float*)d_in[3];
    const float* b1   = (const float*)d_in[4];
    const float* W2   = (const float*)d_in[5];
    const float* b2   = (const float*)d_in[6];
    const float* Wx   = (const float*)d_in[7];
    const float* bx   = (const float*)d_in[8];
    float* out = (float*)d_out;

    k_attn  <<<512, 512>>>(maps, W1, b1, W2, b2);
    k_winner<<<NP / 256, 256>>>(Lix);
    k_count <<<NP / 256, 256>>>(Lix);
    k_scan  <<<1, 1024>>>();
    k_fill  <<<NP / 256, 256>>>(Lix);
    k_agg   <<<Mn, 256>>>(Lix, x);
    k_gemm  <<<NP / 256, 256>>>(Wx, bx, out);
    k_clean <<<NP / 256, 256>>>(Lix);
}

// round 3
// speedup vs baseline: 1.0111x; 1.0111x over previous
#include <cuda_runtime.h>

#define Mn   4096
#define NNB  16
#define Gn   4
#define INF  32
#define OUTF 32
#define LOCF 8
#define LHID 128
#define Bn   16
#define NP   (Mn * NNB)   // 65536 node-neighbor pairs

// ---------------- device scratch (static, zero-initialized at load) ----------
__device__ float4 d_attn4[NP];              // attn[n] packed over g (x,y,z,w = g0..g3)
__device__ int    d_winner[Mn * Mn];        // stores n+1 of last writer; 0 = empty (64MB)
__device__ int    d_counts[Mn];
__device__ int    d_rowPtr[Mn + 1];
__device__ int    d_cursor[Mn];
__device__ int    d_elist[NP];
__device__ float  d_agg[(size_t)Bn * Mn * Gn * INF];   // [b*M+i][g*32+f], 32MB

// ---------------- Stage 1: edge MLP + per-node softmax -----------------------
// grid 512 blocks x 512 threads; block handles 8 nodes x 16 nn x 4 g = 512 pairs
__global__ void __launch_bounds__(512) k_attn(
    const float* __restrict__ maps, const float* __restrict__ W1,
    const float* __restrict__ b1,   const float* __restrict__ W2,
    const float* __restrict__ b2)
{
    __shared__ float4 sW1[Gn * LHID * 2];   // W1 row (8 floats) as 2x float4
    __shared__ float2 sWB[Gn * LHID];       // (W2[k], b1[k])

    int t = threadIdx.x;
    for (int i = t; i < Gn * LHID * 2; i += 512) sW1[i] = ((const float4*)W1)[i];
    for (int i = t; i < Gn * LHID;     i += 512) sWB[i] = make_float2(W2[i], b1[i]);
    __syncthreads();

    int nodeL = t >> 6;            // 0..7
    int g     = (t >> 4) & 3;      // 0..3
    int nn    = t & 15;            // 0..15
    int node  = blockIdx.x * 8 + nodeL;
    int n     = node * NNB + nn;

    const float4* mp = (const float4*)(maps + (size_t)n * LOCF);
    float4 m0 = mp[0], m1 = mp[1];

    float ctx = b2[g];
    int base = g * LHID;
    #pragma unroll 4
    for (int k = 0; k < LHID; k++) {
        float4 wa = sW1[(base + k) * 2];
        float4 wb = sW1[(base + k) * 2 + 1];
        float2 w2b1 = sWB[base + k];
        float pre = w2b1.y
                  + m0.x * wa.x + m0.y * wa.y + m0.z * wa.z + m0.w * wa.w
                  + m1.x * wb.x + m1.y * wb.y + m1.z * wb.z + m1.w * wb.w;
        // tanh(pre) = 1 - 2/(exp(2*pre)+1); exact at +-inf, ~1e-6 rel error
        float e  = __expf(2.0f * pre);
        float th = 1.0f - __fdividef(2.0f, e + 1.0f);
        ctx = fmaf(w2b1.x, th, ctx);
    }

    // softmax over the 16 nn of (node, g): groups of 16 consecutive lanes
    float mx = ctx;
    #pragma unroll
    for (int o = 8; o; o >>= 1) mx = fmaxf(mx, __shfl_xor_sync(0xffffffffu, mx, o));
    float ev = __expf(ctx - mx);
    float s = ev;
    #pragma unroll
    for (int o = 8; o; o >>= 1) s += __shfl_xor_sync(0xffffffffu, s, o);
    ((float*)d_attn4)[(size_t)n * 4 + g] = ev / s;
}

// ---------------- Stage 2: duplicate resolution + CSR build ------------------
__global__ void k_winner(const int* __restrict__ L_idx) {
    int n = blockIdx.x * 256 + threadIdx.x;
    atomicMax(&d_winner[L_idx[n]], n + 1);
}

__global__ void k_count(const int* __restrict__ L_idx) {
    int n = blockIdx.x * 256 + threadIdx.x;
    int idx = L_idx[n];
    if (d_winner[idx] == n + 1) atomicAdd(&d_counts[idx >> 12], 1);
}

__global__ void __launch_bounds__(1024) k_scan() {
    __shared__ int s[1024];
    int t = threadIdx.x;
    int c0 = d_counts[t * 4 + 0], c1 = d_counts[t * 4 + 1];
    int c2 = d_counts[t * 4 + 2], c3 = d_counts[t * 4 + 3];
    int p1 = c0, p2 = c0 + c1, p3 = c0 + c1 + c2, tot = p3 + c3;
    s[t] = tot;
    __syncthreads();
    for (int off = 1; off < 1024; off <<= 1) {
        int v = (t >= off) ? s[t - off] : 0;
        __syncthreads();
        s[t] += v;
        __syncthreads();
    }
    int bpre = t ? s[t - 1] : 0;
    d_rowPtr[t * 4 + 0] = bpre;      d_cursor[t * 4 + 0] = bpre;
    d_rowPtr[t * 4 + 1] = bpre + p1; d_cursor[t * 4 + 1] = bpre + p1;
    d_rowPtr[t * 4 + 2] = bpre + p2; d_cursor[t * 4 + 2] = bpre + p2;
    d_rowPtr[t * 4 + 3] = bpre + p3; d_cursor[t * 4 + 3] = bpre + p3;
    if (t == 1023) d_rowPtr[Mn] = s[1023];
}

__global__ void k_fill(const int* __restrict__ L_idx) {
    int n = blockIdx.x * 256 + threadIdx.x;
    int idx = L_idx[n];
    if (d_winner[idx] == n + 1) {
        int pos = atomicAdd(&d_cursor[idx >> 12], 1);
        d_elist[pos] = n;
    }
}

// ---------------- Stage 3: row-gather aggregation ----------------------------
// one block per row i; thread = (b, f-pair); 8 accumulators (4 g x 2 f)
__global__ void __launch_bounds__(256) k_agg(
    const int* __restrict__ L_idx, const float* __restrict__ x)
{
    int i = blockIdx.x;
    int t = threadIdx.x;
    int b = t >> 4, fh = t & 15;
    int e0 = d_rowPtr[i], e1 = d_rowPtr[i + 1];

    float2 acc0 = {0.f, 0.f}, acc1 = {0.f, 0.f}, acc2 = {0.f, 0.f}, acc3 = {0.f, 0.f};
    const float2* x2 = (const float2*)x;

    for (int e = e0; e < e1; e++) {
        int n = d_elist[e];
        int j = L_idx[n] & (Mn - 1);
        float4 a = d_attn4[n];
        float2 xv = x2[(size_t)(b * Mn + j) * 16 + fh];
        acc0.x = fmaf(a.x, xv.x, acc0.x); acc0.y = fmaf(a.x, xv.y, acc0.y);
        acc1.x = fmaf(a.y, xv.x, acc1.x); acc1.y = fmaf(a.y, xv.y, acc1.y);
        acc2.x = fmaf(a.z, xv.x, acc2.x); acc2.y = fmaf(a.z, xv.y, acc2.y);
        acc3.x = fmaf(a.w, xv.x, acc3.x); acc3.y = fmaf(a.w, xv.y, acc3.y);
    }

    float2* agg2 = (float2*)d_agg;
    size_t rbase = (size_t)(b * Mn + i) * 64 + fh;   // [r][g*16+fh] in float2
    agg2[rbase + 0 * 16] = acc0;
    agg2[rbase + 1 * 16] = acc1;
    agg2[rbase + 2 * 16] = acc2;
    agg2[rbase + 3 * 16] = acc3;
}

// ---------------- Stage 4: dense GEMM (65536x128)@(128x32)+bx ----------------
// block: 256 rows x 32 cols; thread: 8 rows x 4 cols
__global__ void __launch_bounds__(256) k_gemm(
    const float* __restrict__ Wx, const float* __restrict__ bx,
    float* __restrict__ out)
{
    __shared__ float4 sW[LHID * 8];    // Wx[k][o] as float4 over o: sW[k*8 + oc]
    int t = threadIdx.x;
    for (int i = t; i < LHID * 8; i += 256) sW[i] = ((const float4*)Wx)[i];
    __syncthreads();

    int tcol = t & 7;        // o block: [tcol*4, tcol*4+4)
    int trow = t >> 3;       // 0..31
    int r0 = blockIdx.x * 256 + trow * 8;

    const float4* A4 = (const float4*)d_agg;
    float4 acc[8];
    #pragma unroll
    for (int rr = 0; rr < 8; rr++) acc[rr] = make_float4(0.f, 0.f, 0.f, 0.f);

    #pragma unroll 1
    for (int k4 = 0; k4 < 32; k4++) {
        float4 w0 = sW[(k4 * 4 + 0) * 8 + tcol];
        float4 w1 = sW[(k4 * 4 + 1) * 8 + tcol];
        float4 w2 = sW[(k4 * 4 + 2) * 8 + tcol];
        float4 w3 = sW[(k4 * 4 + 3) * 8 + tcol];
        #pragma unroll
        for (int rr = 0; rr < 8; rr++) {
            float4 av = A4[(size_t)(r0 + rr) * 32 + k4];
            acc[rr].x = fmaf(av.x, w0.x, fmaf(av.y, w1.x, fmaf(av.z, w2.x, fmaf(av.w, w3.x, acc[rr].x))));
            acc[rr].y = fmaf(av.x, w0.y, fmaf(av.y, w1.y, fmaf(av.z, w2.y, fmaf(av.w, w3.y, acc[rr].y))));
            acc[rr].z = fmaf(av.x, w0.z, fmaf(av.y, w1.z, fmaf(av.z, w2.z, fmaf(av.w, w3.z, acc[rr].z))));
            acc[rr].w = fmaf(av.x, w0.w, fmaf(av.y, w1.w, fmaf(av.z, w2.w, fmaf(av.w, w3.w, acc[rr].w))));
        }
    }

    float4 bxv = ((const float4*)bx)[tcol];
    #pragma unroll
    for (int rr = 0; rr < 8; rr++) {
        float4 v;
        v.x = acc[rr].x + bxv.x; v.y = acc[rr].y + bxv.y;
        v.z = acc[rr].z + bxv.z; v.w = acc[rr].w + bxv.w;
        ((float4*)out)[(size_t)(r0 + rr) * 8 + tcol] = v;
    }
}

// ---------------- cleanup: restore scratch invariants for next launch --------
__global__ void k_clean(const int* __restrict__ L_idx) {
    int n = blockIdx.x * 256 + threadIdx.x;
    d_winner[L_idx[n]] = 0;
    if (n < Mn) d_counts[n] = 0;
}

// ---------------- launch ------------------------------------------------------
extern "C" void kernel_launch(void* const* d_in, const int* in_sizes, int n_in,
                              void* d_out, int out_size)
{
    const float* x    = (const float*)d_in[0];
    const float* maps = (const float*)d_in[1];
    const int*   Lix  = (const int*)  d_in[2];
    const float* W1   = (const float*)d_in[3];
    const float* b1   = (const float*)d_in[4];
    const float* W2   = (const float*)d_in[5];
    const float* b2   = (const float*)d_in[6];
    const float* Wx   = (const float*)d_in[7];
    const float* bx   = (const float*)d_in[8];
    float* out = (float*)d_out;

    k_attn  <<<512, 512>>>(maps, W1, b1, W2, b2);
    k_winner<<<NP / 256, 256>>>(Lix);
    k_count <<<NP / 256, 256>>>(Lix);
    k_scan  <<<1, 1024>>>();
    k_fill  <<<NP / 256, 256>>>(Lix);
    k_agg   <<<Mn, 256>>>(Lix, x);
    k_gemm  <<<NP / 256, 256>>>(Wx, bx, out);
    k_clean <<<NP / 256, 256>>>(Lix);
}